// round 2
// baseline (speedup 1.0000x reference)
#include <cuda_runtime.h>
#include <cstdint>
#include <cstddef>

// ---------------------------------------------------------------------------
// Problem dims
// ---------------------------------------------------------------------------
#define B_  32
#define C_  512
#define T_  16
#define HW_ 49
#define NA_ 441
#define PN_ 300
#define K1_ 13824            // 512*27
#define K2_ 73728            // 512*16*9

// output layout: rois [32,300,5] | cls_prob [32,18,7,7] | bbox_pred [32,36,7,7]
#define ROIS_OFF 0
#define CLS_OFF  48000
#define BBOX_OFF 76224

// ---------------------------------------------------------------------------
// Scratch (static device globals; no allocation)
// ---------------------------------------------------------------------------
__device__ float g_w1t[(size_t)K1_ * C_];            // [k][oc] transposed conv1 weights
__device__ float g_w2t[(size_t)K2_ * C_];            // [k][oc] transposed conv2 weights
__device__ float g_x  [(size_t)B_ * C_ * T_ * HW_];  // conv1 output (relu)
__device__ float g_f16[(size_t)B_ * C_ * HW_];       // conv2 output (relu)
__device__ float g_prop[B_ * NA_ * 4];               // decoded + clipped proposals
__device__ float g_scr [B_ * NA_];                   // fg scores

// base anchors (faithful port of generate_anchors(16,[0.5,1,2],[4,8,16]))
__constant__ float c_anch[9][4] = {
    {-38.f,  -16.f,  53.f,  31.f},
    {-84.f,  -40.f,  99.f,  55.f},
    {-176.f, -88.f,  191.f, 103.f},
    {-24.f,  -24.f,  39.f,  39.f},
    {-56.f,  -56.f,  71.f,  71.f},
    {-120.f, -120.f, 135.f, 135.f},
    {-14.f,  -36.f,  29.f,  51.f},
    {-36.f,  -80.f,  51.f,  95.f},
    {-80.f,  -168.f, 95.f,  183.f}};

// ---------------------------------------------------------------------------
// f32x2 packed-FMA helpers (FFMA2 — only reachable via PTX)
// ---------------------------------------------------------------------------
__device__ __forceinline__ unsigned long long pack2(float x) {
    unsigned long long r;
    asm("mov.b64 %0,{%1,%1};" : "=l"(r) : "f"(x));
    return r;
}
__device__ __forceinline__ void fma2(unsigned long long& d,
                                     unsigned long long a,
                                     unsigned long long b) {
    asm("fma.rn.f32x2 %0,%1,%2,%0;" : "+l"(d) : "l"(a), "l"(b));
}
__device__ __forceinline__ void unpack2(unsigned long long v, float& lo, float& hi) {
    asm("mov.b64 {%0,%1},%2;" : "=f"(lo), "=f"(hi) : "l"(v));
}

// ---------------------------------------------------------------------------
// Weight transpose: in [512][K] -> out [K][512]
// ---------------------------------------------------------------------------
__global__ void tr_k(const float* __restrict__ in, float* __restrict__ out, int K) {
    __shared__ float t[32][33];
    int kb = blockIdx.x << 5, ob = blockIdx.y << 5;
    int tx = threadIdx.x, ty = threadIdx.y;
#pragma unroll
    for (int j = 0; j < 32; j += 8)
        t[ty + j][tx] = in[(size_t)(ob + ty + j) * K + kb + tx];
    __syncthreads();
#pragma unroll
    for (int j = 0; j < 32; j += 8)
        out[(size_t)(kb + ty + j) * 512 + ob + tx] = t[tx][ty + j];
}

// ---------------------------------------------------------------------------
// Conv1: 3x3x3, pad(1,1,1), relu.  grid=(8 oc-tiles, 512 (b,t)), block=224
// block = 8 ocg x 7 h x 4 ksplit; each thread accumulates 8 oc x 7 w.
// ---------------------------------------------------------------------------
__global__ __launch_bounds__(224) void conv1_k(const float* __restrict__ bf,
                                               const float* __restrict__ bias) {
    extern __shared__ float sm[];
    float* sw = sm;           // [216][64]  weights chunk (13824 floats)
    float* sx = sm + 13824;   // [8][3][81] padded input patch (1944 floats)

    int tid = threadIdx.x;
    int ocg = tid & 7;
    int hh  = (tid >> 3) % 7;
    int ks  = tid / 56;
    int octile = blockIdx.x;
    int b = blockIdx.y >> 4, t = blockIdx.y & 15;

    unsigned long long acc[7][4];
#pragma unroll
    for (int w = 0; w < 7; ++w)
#pragma unroll
        for (int q = 0; q < 4; ++q) acc[w][q] = 0ull;

    for (int ch = 0; ch < 64; ++ch) {       // ic chunks of 8
        __syncthreads();
        int kb = ch * 216;
        // stage weights [216 k][64 oc]
        for (int i = tid; i < 216 * 16; i += 224) {
            int r = i >> 4, c4 = i & 15;
            *(float4*)&sw[r * 64 + c4 * 4] =
                *(const float4*)&g_w1t[(size_t)(kb + r) * 512 + octile * 64 + c4 * 4];
        }
        // stage padded input patch [8 ic][3 dt][9][9]
        int icb = ch * 8;
        for (int i = tid; i < 1944; i += 224) {
            int ic = i / 243, rem = i - ic * 243;
            int dt = rem / 81, pos = rem - dt * 81;
            int r = pos / 9, c = pos - r * 9;
            int tt = t + dt - 1;
            float v = 0.f;
            if (r >= 1 && r <= 7 && c >= 1 && c <= 7 && tt >= 0 && tt < 16)
                v = bf[(((size_t)b * 512 + icb + ic) * 16 + tt) * 49 + (r - 1) * 7 + (c - 1)];
            sx[i] = v;
        }
        __syncthreads();

#pragma unroll 1
        for (int i2 = 0; i2 < 2; ++i2) {
            int ic = ks * 2 + i2;
            const float* xb = &sx[ic * 243];
            const float* wb = &sw[ic * 27 * 64 + ocg * 8];
#pragma unroll 1
            for (int dt = 0; dt < 3; ++dt) {
#pragma unroll
                for (int dh = 0; dh < 3; ++dh)
#pragma unroll
                    for (int dw = 0; dw < 3; ++dw) {
                        const ulonglong2* wp =
                            (const ulonglong2*)&wb[(dt * 9 + dh * 3 + dw) * 64];
                        ulonglong2 w0 = wp[0], w1 = wp[1];
                        const float* xr = &xb[dt * 81 + (hh + dh) * 9 + dw];
#pragma unroll
                        for (int w = 0; w < 7; ++w) {
                            unsigned long long xx = pack2(xr[w]);
                            fma2(acc[w][0], w0.x, xx);
                            fma2(acc[w][1], w0.y, xx);
                            fma2(acc[w][2], w1.x, xx);
                            fma2(acc[w][3], w1.y, xx);
                        }
                    }
            }
        }
    }

    float f[56];
#pragma unroll
    for (int w = 0; w < 7; ++w)
#pragma unroll
        for (int q = 0; q < 4; ++q)
            unpack2(acc[w][q], f[w * 8 + q * 2], f[w * 8 + q * 2 + 1]);

    __syncthreads();
    if (ks > 0) {
        float* dst = &sw[((ks - 1) * 56 + ocg * 7 + hh) * 57];
#pragma unroll
        for (int j = 0; j < 56; ++j) dst[j] = f[j];
    }
    __syncthreads();
    if (ks == 0) {
        for (int s = 0; s < 3; ++s) {
            const float* src = &sw[(s * 56 + ocg * 7 + hh) * 57];
#pragma unroll
            for (int j = 0; j < 56; ++j) f[j] += src[j];
        }
        int ocb = octile * 64 + ocg * 8;
#pragma unroll
        for (int j = 0; j < 8; ++j) {
            float bv = bias[ocb + j];
#pragma unroll
            for (int w = 0; w < 7; ++w) {
                float v = f[w * 8 + j] + bv;
                g_x[(((size_t)b * 512 + ocb + j) * 16 + t) * 49 + hh * 7 + w] =
                    fmaxf(v, 0.f);
            }
        }
    }
}

// ---------------------------------------------------------------------------
// Conv2: 16x3x3, pad(0,1,1), relu.  grid=(8 oc-tiles, 32 b), block=224
// ---------------------------------------------------------------------------
__global__ __launch_bounds__(224) void conv2_k(const float* __restrict__ bias) {
    extern __shared__ float sm[];
    float* sw = sm;           // [288][64]   (18432 floats)
    float* sx = sm + 18432;   // [2][16][81] (2592 floats)

    int tid = threadIdx.x;
    int ocg = tid & 7;
    int hh  = (tid >> 3) % 7;
    int ks  = tid / 56;
    int octile = blockIdx.x, b = blockIdx.y;

    unsigned long long acc[7][4];
#pragma unroll
    for (int w = 0; w < 7; ++w)
#pragma unroll
        for (int q = 0; q < 4; ++q) acc[w][q] = 0ull;

    for (int ch = 0; ch < 256; ++ch) {      // ic chunks of 2
        __syncthreads();
        int kb = ch * 288, icb = ch * 2;
        for (int i = tid; i < 288 * 16; i += 224) {
            int r = i >> 4, c4 = i & 15;
            *(float4*)&sw[r * 64 + c4 * 4] =
                *(const float4*)&g_w2t[(size_t)(kb + r) * 512 + octile * 64 + c4 * 4];
        }
        for (int i = tid; i < 2592; i += 224) {
            int ic = i / 1296, rem = i - ic * 1296;
            int tt = rem / 81, pos = rem - tt * 81;
            int r = pos / 9, c = pos - r * 9;
            float v = 0.f;
            if (r >= 1 && r <= 7 && c >= 1 && c <= 7)
                v = g_x[(((size_t)b * 512 + icb + ic) * 16 + tt) * 49 + (r - 1) * 7 + (c - 1)];
            sx[i] = v;
        }
        __syncthreads();

#pragma unroll 1
        for (int i2 = 0; i2 < 2; ++i2) {
#pragma unroll 1
            for (int tq = 0; tq < 4; ++tq) {
                int tt = ks * 4 + tq;
                const float* xb = &sx[i2 * 1296 + tt * 81];
                const float* wb = &sw[(i2 * 144 + tt * 9) * 64 + ocg * 8];
#pragma unroll
                for (int dh = 0; dh < 3; ++dh)
#pragma unroll
                    for (int dw = 0; dw < 3; ++dw) {
                        const ulonglong2* wp = (const ulonglong2*)&wb[(dh * 3 + dw) * 64];
                        ulonglong2 w0 = wp[0], w1 = wp[1];
                        const float* xr = &xb[(hh + dh) * 9 + dw];
#pragma unroll
                        for (int w = 0; w < 7; ++w) {
                            unsigned long long xx = pack2(xr[w]);
                            fma2(acc[w][0], w0.x, xx);
                            fma2(acc[w][1], w0.y, xx);
                            fma2(acc[w][2], w1.x, xx);
                            fma2(acc[w][3], w1.y, xx);
                        }
                    }
            }
        }
    }

    float f[56];
#pragma unroll
    for (int w = 0; w < 7; ++w)
#pragma unroll
        for (int q = 0; q < 4; ++q)
            unpack2(acc[w][q], f[w * 8 + q * 2], f[w * 8 + q * 2 + 1]);

    __syncthreads();
    if (ks > 0) {
        float* dst = &sw[((ks - 1) * 56 + ocg * 7 + hh) * 57];
#pragma unroll
        for (int j = 0; j < 56; ++j) dst[j] = f[j];
    }
    __syncthreads();
    if (ks == 0) {
        for (int s = 0; s < 3; ++s) {
            const float* src = &sw[(s * 56 + ocg * 7 + hh) * 57];
#pragma unroll
            for (int j = 0; j < 56; ++j) f[j] += src[j];
        }
        int ocb = octile * 64 + ocg * 8;
#pragma unroll
        for (int j = 0; j < 8; ++j) {
            float bv = bias[ocb + j];
#pragma unroll
            for (int w = 0; w < 7; ++w) {
                float v = f[w * 8 + j] + bv;
                g_f16[((size_t)b * 512 + ocb + j) * 49 + hh * 7 + w] = fmaxf(v, 0.f);
            }
        }
    }
}

// ---------------------------------------------------------------------------
// Heads: 1x1 convs (cls 18 + bbox 36), pairwise softmax, bbox decode + clip.
// One CTA per batch element.
// ---------------------------------------------------------------------------
__global__ __launch_bounds__(256) void heads_k(const float* __restrict__ cw,
                                               const float* __restrict__ cb,
                                               const float* __restrict__ bw,
                                               const float* __restrict__ bb,
                                               const float* __restrict__ info,
                                               float* __restrict__ out) {
    extern __shared__ float sm[];
    float* sf = sm;          // [512][49] f16 features
    float* ss = sm + 25088;  // [54][49] raw head outputs

    int b = blockIdx.x, tid = threadIdx.x;
    for (int i = tid; i < 25088; i += 256) sf[i] = g_f16[(size_t)b * 25088 + i];
    __syncthreads();

    for (int idx = tid; idx < 54 * 49; idx += 256) {
        int o = idx / 49, p = idx - o * 49;
        const float* wr = (o < 18) ? &cw[o * 512] : &bw[(o - 18) * 512];
        float bia = (o < 18) ? cb[o] : bb[o - 18];
        float a = 0.f;
        for (int c = 0; c < 512; ++c) a += sf[c * 49 + p] * __ldg(&wr[c]);
        ss[idx] = a + bia;
    }
    __syncthreads();

    // pairwise softmax (channel a vs 9+a) -> cls_prob + fg scores
    for (int idx = tid; idx < 441; idx += 256) {
        int a9 = idx / 49, p = idx - a9 * 49;
        float bg = ss[a9 * 49 + p], fg = ss[(9 + a9) * 49 + p];
        float m = fmaxf(bg, fg);
        float e0 = expf(bg - m), e1 = expf(fg - m);
        float s = e0 + e1;
        float p0 = e0 / s, p1 = e1 / s;
        out[CLS_OFF + b * 882 + a9 * 49 + p] = p0;
        out[CLS_OFF + b * 882 + (9 + a9) * 49 + p] = p1;
        g_scr[b * 441 + p * 9 + a9] = p1;   // score idx = (h*7+w)*9 + a
    }
    // raw bbox_pred out
    for (int idx = tid; idx < 36 * 49; idx += 256)
        out[BBOX_OFF + b * 1764 + idx] = ss[882 + idx];

    // decode + clip
    float imh = info[b * 3 + 0], imw = info[b * 3 + 1];
    for (int i = tid; i < 441; i += 256) {
        int k = i / 9, a = i - k * 9;
        int hp = k / 7, wp = k - hp * 7;
        float d0 = ss[(18 + a * 4 + 0) * 49 + k];
        float d1 = ss[(18 + a * 4 + 1) * 49 + k];
        float d2 = ss[(18 + a * 4 + 2) * 49 + k];
        float d3 = ss[(18 + a * 4 + 3) * 49 + k];
        float x1 = c_anch[a][0] + wp * 16.f, y1 = c_anch[a][1] + hp * 16.f;
        float x2 = c_anch[a][2] + wp * 16.f, y2 = c_anch[a][3] + hp * 16.f;
        float aw = x2 - x1 + 1.f, ah = y2 - y1 + 1.f;
        float cx = x1 + 0.5f * aw, cy = y1 + 0.5f * ah;
        float pcx = d0 * aw + cx, pcy = d1 * ah + cy;
        float pw = expf(d2) * aw, ph = expf(d3) * ah;
        float bx1 = pcx - 0.5f * pw, by1 = pcy - 0.5f * ph;
        float bx2 = pcx + 0.5f * pw, by2 = pcy + 0.5f * ph;
        bx1 = fminf(fmaxf(bx1, 0.f), imw - 1.f);
        by1 = fminf(fmaxf(by1, 0.f), imh - 1.f);
        bx2 = fminf(fmaxf(bx2, 0.f), imw - 1.f);
        by2 = fminf(fmaxf(by2, 0.f), imh - 1.f);
        float* pr = &g_prop[(b * 441 + i) * 4];
        pr[0] = bx1; pr[1] = by1; pr[2] = bx2; pr[3] = by2;
    }
}

// ---------------------------------------------------------------------------
// NMS: stable rank-sort (score desc, idx asc), greedy suppression, compact.
// One CTA per batch element.
// ---------------------------------------------------------------------------
__global__ __launch_bounds__(448) void nms_k(float* __restrict__ out) {
    __shared__ float ux1[441], uy1[441], ux2[441], uy2[441], usc[441];
    __shared__ float sx1[441], sy1[441], sx2[441], sy2[441], sar[441];
    __shared__ int keep[441];

    int b = blockIdx.x, tid = threadIdx.x;
    for (int i = tid; i < 441; i += 448) {
        const float* pr = &g_prop[(b * 441 + i) * 4];
        ux1[i] = pr[0]; uy1[i] = pr[1]; ux2[i] = pr[2]; uy2[i] = pr[3];
        usc[i] = g_scr[b * 441 + i];
        keep[i] = 1;
    }
    __syncthreads();

    // stable rank sort: rank = #{j: sc_j > sc_i or (sc_j == sc_i and j < i)}
    for (int i = tid; i < 441; i += 448) {
        float si = usc[i];
        int r = 0;
        for (int j = 0; j < 441; ++j) {
            float sj = usc[j];
            r += (sj > si) || (sj == si && j < i);
        }
        sx1[r] = ux1[i]; sy1[r] = uy1[i]; sx2[r] = ux2[i]; sy2[r] = uy2[i];
        sar[r] = (ux2[i] - ux1[i] + 1.f) * (uy2[i] - uy1[i] + 1.f);
    }

    // greedy suppression (sequential over sorted order)
    for (int i = 0; i < 440; ++i) {
        __syncthreads();
        if (keep[i]) {
            float xi1 = sx1[i], yi1 = sy1[i], xi2 = sx2[i], yi2 = sy2[i], ai = sar[i];
            for (int j = i + 1 + tid; j < 441; j += 448) {
                if (!keep[j]) continue;
                float xx1 = fmaxf(xi1, sx1[j]);
                float yy1 = fmaxf(yi1, sy1[j]);
                float xx2 = fminf(xi2, sx2[j]);
                float yy2 = fminf(yi2, sy2[j]);
                float iw = fmaxf(xx2 - xx1 + 1.f, 0.f);
                float ih = fmaxf(yy2 - yy1 + 1.f, 0.f);
                float inter = iw * ih;
                float iou = inter / (ai + sar[j] - inter);
                if (iou > 0.7f) keep[j] = 0;
            }
        }
    }
    __syncthreads();

    // init rows: batch index col + zero boxes
    for (int r = tid; r < 300; r += 448) {
        float* o = &out[ROIS_OFF + (b * 300 + r) * 5];
        o[0] = (float)b; o[1] = 0.f; o[2] = 0.f; o[3] = 0.f; o[4] = 0.f;
    }
    __syncthreads();
    // compact kept boxes in sorted order
    for (int i = tid; i < 441; i += 448) {
        if (keep[i]) {
            int pos = 0;
            for (int j = 0; j < i; ++j) pos += keep[j];
            if (pos < 300) {
                float* o = &out[ROIS_OFF + (b * 300 + pos) * 5];
                o[1] = sx1[i]; o[2] = sy1[i]; o[3] = sx2[i]; o[4] = sy2[i];
            }
        }
    }
}

// ---------------------------------------------------------------------------
// Launch
// ---------------------------------------------------------------------------
extern "C" void kernel_launch(void* const* d_in, const int* in_sizes, int n_in,
                              void* d_out, int out_size) {
    const float* base = (const float*)d_in[0];
    const float* info = (const float*)d_in[1];
    const float* w1   = (const float*)d_in[4];
    const float* b1   = (const float*)d_in[5];
    const float* w2   = (const float*)d_in[6];
    const float* b2   = (const float*)d_in[7];
    const float* cw   = (const float*)d_in[8];
    const float* cb   = (const float*)d_in[9];
    const float* bw   = (const float*)d_in[10];
    const float* bb   = (const float*)d_in[11];
    float* out = (float*)d_out;

    cudaFuncSetAttribute(conv1_k, cudaFuncAttributeMaxDynamicSharedMemorySize, 63072);
    cudaFuncSetAttribute(conv2_k, cudaFuncAttributeMaxDynamicSharedMemorySize, 84096);
    cudaFuncSetAttribute(heads_k, cudaFuncAttributeMaxDynamicSharedMemorySize, 110936);

    float *pw1t = nullptr, *pw2t = nullptr;
    cudaGetSymbolAddress((void**)&pw1t, g_w1t);
    cudaGetSymbolAddress((void**)&pw2t, g_w2t);

    dim3 tb(32, 8);
    tr_k<<<dim3(K1_ / 32, 16), tb>>>(w1, pw1t, K1_);
    tr_k<<<dim3(K2_ / 32, 16), tb>>>(w2, pw2t, K2_);
    conv1_k<<<dim3(8, 512), 224, 63072>>>(base, b1);
    conv2_k<<<dim3(8, 32), 224, 84096>>>(b2);
    heads_k<<<32, 256, 110936>>>(cw, cb, bw, bb, info, out);
    nms_k<<<32, 448>>>(out);
}

// round 4
// speedup vs baseline: 1.0260x; 1.0260x over previous
#include <cuda_runtime.h>
#include <cstdint>
#include <cstddef>

// ---------------------------------------------------------------------------
// Problem dims
// ---------------------------------------------------------------------------
#define B_  32
#define C_  512
#define T_  16
#define NA_ 441
#define K1_ 13824            // 512*27
#define K2_ 73728            // 512*16*9

// output layout: rois [32,300,5] | cls_prob [32,18,7,7] | bbox_pred [32,36,7,7]
#define ROIS_OFF 0
#define CLS_OFF  48000
#define BBOX_OFF 76224

// padded/duplicated plane: 9 rows x 10 cols (col9=0), each value duplicated
// -> 9*20 = 180 floats, padded to 192 (16B multiple). Pair (x,x) via LDS.64.
#define PLN 192

// conv1 tiling
#define BUF1 5760            // floats per buffer: 108*32 weights + 4*3*192 x
#define NCH1 128
// conv2 tiling
#define BUF2 7680            // floats per buffer: 144*32 weights + 2*8*192 x
#define NCH2 256

// ---------------------------------------------------------------------------
// Scratch (static device globals; no allocation)
// ---------------------------------------------------------------------------
__device__ float g_w1t[(size_t)K1_ * C_];                  // [k][oc]
__device__ float g_w2t[(size_t)K2_ * C_];                  // [k][oc]
__device__ float g_bfpad[(size_t)B_ * C_ * 18 * PLN];      // padded+dup input (t in [-1,16])
__device__ float g_xpad [(size_t)B_ * C_ * 16 * PLN];      // padded+dup conv1 output
__device__ float g_p2   [(size_t)2 * B_ * C_ * 49];        // conv2 t-split partials
__device__ float g_prop[B_ * NA_ * 4];
__device__ float g_scr [B_ * NA_];

__constant__ float c_anch[9][4] = {
    {-38.f,  -16.f,  53.f,  31.f},
    {-84.f,  -40.f,  99.f,  55.f},
    {-176.f, -88.f,  191.f, 103.f},
    {-24.f,  -24.f,  39.f,  39.f},
    {-56.f,  -56.f,  71.f,  71.f},
    {-120.f, -120.f, 135.f, 135.f},
    {-14.f,  -36.f,  29.f,  51.f},
    {-36.f,  -80.f,  51.f,  95.f},
    {-80.f,  -168.f, 95.f,  183.f}};

// ---------------------------------------------------------------------------
// PTX helpers
// ---------------------------------------------------------------------------
__device__ __forceinline__ void fma2(unsigned long long& d,
                                     unsigned long long a,
                                     unsigned long long b) {
    asm("fma.rn.f32x2 %0,%1,%2,%0;" : "+l"(d) : "l"(a), "l"(b));
}
__device__ __forceinline__ void unpack2(unsigned long long v, float& lo, float& hi) {
    asm("mov.b64 {%0,%1},%2;" : "=f"(lo), "=f"(hi) : "l"(v));
}
__device__ __forceinline__ void cpa16(unsigned dst, const void* src) {
    asm volatile("cp.async.cg.shared.global [%0],[%1],16;" :: "r"(dst), "l"(src));
}
__device__ __forceinline__ void cpcommit() { asm volatile("cp.async.commit_group;"); }
__device__ __forceinline__ void cpwait1()  { asm volatile("cp.async.wait_group 1;"); }
__device__ __forceinline__ void cpwait0()  { asm volatile("cp.async.wait_group 0;"); }

// ---------------------------------------------------------------------------
// Weight transpose: in [512][K] -> out [K][512]
// ---------------------------------------------------------------------------
__global__ void tr_k(const float* __restrict__ in, float* __restrict__ out, int K) {
    __shared__ float t[32][33];
    int kb = blockIdx.x << 5, ob = blockIdx.y << 5;
    int tx = threadIdx.x, ty = threadIdx.y;
#pragma unroll
    for (int j = 0; j < 32; j += 8)
        t[ty + j][tx] = in[(size_t)(ob + ty + j) * K + kb + tx];
    __syncthreads();
#pragma unroll
    for (int j = 0; j < 32; j += 8)
        out[(size_t)(kb + ty + j) * 512 + ob + tx] = t[tx][ty + j];
}

// ---------------------------------------------------------------------------
// Build padded+duplicated input planes. 1 float per thread.
// plane layout: row r (0..8) x col (0..9, col9=0), duplicated -> j = r*20 + 2*col{+1}
// ---------------------------------------------------------------------------
__global__ void pad_in_k(const float* __restrict__ bf) {
    size_t i = (size_t)blockIdx.x * 256 + threadIdx.x;   // total = 32*512*18*192
    int j = (int)(i % PLN);
    size_t r1 = i / PLN;
    int tp = (int)(r1 % 18);
    size_t bc = r1 / 18;
    float v = 0.f;
    if (j < 180 && tp >= 1 && tp <= 16) {
        int row = j / 20, col = (j % 20) >> 1;
        if (row >= 1 && row <= 7 && col >= 1 && col <= 7)
            v = bf[bc * 784 + (size_t)(tp - 1) * 49 + (row - 1) * 7 + (col - 1)];
    }
    g_bfpad[i] = v;
}

// zero g_xpad (borders must be zero; interior rewritten by conv1)
__global__ void zero_xpad_k() {
    size_t i = (size_t)blockIdx.x * 256 + threadIdx.x;
    ((float4*)g_xpad)[i] = make_float4(0.f, 0.f, 0.f, 0.f);
}

// ---------------------------------------------------------------------------
// Conv1: 3x3x3 pad(1,1,1) relu. grid=(16 oc-tiles, 512 (b,t)), block=224
// 8 ocg x 7 h x 4 ks; thread: 4 oc x 7 w. cp.async double buffered.
// ---------------------------------------------------------------------------
__global__ __launch_bounds__(224, 3) void conv1_k(const float* __restrict__ bias) {
    extern __shared__ float sm[];
    const int tid = threadIdx.x, ocg = tid & 7, hh = (tid >> 3) % 7, ks = tid / 56;
    const int octile = blockIdx.x, b = blockIdx.y >> 4, t = blockIdx.y & 15;
    const unsigned smb = (unsigned)__cvta_generic_to_shared(sm);

    unsigned long long acc[7][2];
#pragma unroll
    for (int w = 0; w < 7; ++w) { acc[w][0] = 0ull; acc[w][1] = 0ull; }

    auto stage = [&](int ch, int buf) {
        unsigned swd = smb + (unsigned)buf * (BUF1 * 4);
        unsigned sxd = swd + 3456 * 4;
        const float* wsrc = g_w1t + (size_t)(ch * 108) * 512 + octile * 32;
        for (int i = tid; i < 864; i += 224) {       // 108 rows x 32 fl (8x16B)
            int r = i >> 3, c = i & 7;
            cpa16(swd + (unsigned)(r * 128 + c * 16), wsrc + (size_t)r * 512 + c * 4);
        }
        const float* xsrc = g_bfpad + ((size_t)(b * 512 + ch * 4) * 18 + t) * PLN;
        for (int i = tid; i < 576; i += 224) {       // 12 planes x 48 chunks of 16B
            int p = i / 48, q = i - p * 48;
            int il = p / 3, dt = p - il * 3;
            cpa16(sxd + (unsigned)(p * 768 + q * 16),
                  xsrc + ((size_t)il * 18 + dt) * PLN + q * 4);
        }
    };

    auto comp = [&](int buf) {
        const float* swp = sm + buf * BUF1;
        const float* sxp = swp + 3456;
        const float* xic = sxp + ks * (3 * PLN);
        const float* wic = swp + ks * 27 * 32 + ocg * 4;
#pragma unroll 1
        for (int dt = 0; dt < 3; ++dt) {
#pragma unroll
            for (int dh = 0; dh < 3; ++dh) {
                const float* xr = xic + dt * PLN + (hh + dh) * 20;
                unsigned long long xp[9];
#pragma unroll
                for (int e = 0; e < 9; ++e)
                    xp[e] = *(const unsigned long long*)(xr + 2 * e);
#pragma unroll
                for (int dw = 0; dw < 3; ++dw) {
                    ulonglong2 wv =
                        *(const ulonglong2*)(wic + (dt * 9 + dh * 3 + dw) * 32);
#pragma unroll
                    for (int w = 0; w < 7; ++w) {
                        fma2(acc[w][0], wv.x, xp[dw + w]);
                        fma2(acc[w][1], wv.y, xp[dw + w]);
                    }
                }
            }
        }
    };

    stage(0, 0); cpcommit();
#pragma unroll 1
    for (int ch = 0; ch < NCH1; ++ch) {
        if (ch + 1 < NCH1) { stage(ch + 1, (ch + 1) & 1); cpcommit(); cpwait1(); }
        else cpwait0();
        __syncthreads();
        comp(ch & 1);
        __syncthreads();
    }

    float f[28];
#pragma unroll
    for (int w = 0; w < 7; ++w) {
        unpack2(acc[w][0], f[w * 4 + 0], f[w * 4 + 1]);
        unpack2(acc[w][1], f[w * 4 + 2], f[w * 4 + 3]);
    }

    if (ks > 0) {
        float* dst = &sm[((ks - 1) * 56 + hh * 8 + ocg) * 29];
#pragma unroll
        for (int j = 0; j < 28; ++j) dst[j] = f[j];
    }
    __syncthreads();
    if (ks == 0) {
        for (int s = 0; s < 3; ++s) {
            const float* src = &sm[(s * 56 + hh * 8 + ocg) * 29];
#pragma unroll
            for (int j = 0; j < 28; ++j) f[j] += src[j];
        }
        int ocb = octile * 32 + ocg * 4;
#pragma unroll
        for (int j = 0; j < 4; ++j) {
            float bv = bias[ocb + j];
#pragma unroll
            for (int w = 0; w < 7; ++w) {
                float v = fmaxf(f[w * 4 + j] + bv, 0.f);
                size_t o = ((size_t)(b * 512 + ocb + j) * 16 + t) * PLN
                           + (hh + 1) * 20 + 2 * (w + 1);
                g_xpad[o] = v; g_xpad[o + 1] = v;
            }
        }
    }
}

// ---------------------------------------------------------------------------
// Conv2: 16x3x3 pad(0,1,1). grid=(16 oc-tiles, 32 b, 2 t-split), block=224
// Each CTA: 8 t-planes. Partial sums (no bias/relu) -> g_p2.
// ---------------------------------------------------------------------------
__global__ __launch_bounds__(224, 3) void conv2_k() {
    extern __shared__ float sm[];
    const int tid = threadIdx.x, ocg = tid & 7, hh = (tid >> 3) % 7, ks = tid / 56;
    const int octile = blockIdx.x, b = blockIdx.y, ts = blockIdx.z, toff = ts * 8;
    const unsigned smb = (unsigned)__cvta_generic_to_shared(sm);

    unsigned long long acc[7][2];
#pragma unroll
    for (int w = 0; w < 7; ++w) { acc[w][0] = 0ull; acc[w][1] = 0ull; }

    auto stage = [&](int ch, int buf) {
        unsigned swd = smb + (unsigned)buf * (BUF2 * 4);
        unsigned sxd = swd + 4608 * 4;
        int icb = ch * 2;
        for (int i = tid; i < 1152; i += 224) {      // 144 rows x 32 fl
            int r = i >> 3, c = i & 7;
            int il = (r >= 72), rr = r - il * 72;
            size_t gk = ((size_t)(icb + il) * 16 + toff) * 9 + rr;
            cpa16(swd + (unsigned)(r * 128 + c * 16),
                  g_w2t + gk * 512 + octile * 32 + c * 4);
        }
        for (int i = tid; i < 768; i += 224) {       // 16 planes x 48 chunks of 16B
            int p = i / 48, q = i - p * 48;
            int il = p >> 3, tl = p & 7;
            cpa16(sxd + (unsigned)(p * 768 + q * 16),
                  g_xpad + ((size_t)(b * 512 + icb + il) * 16 + toff + tl) * PLN + q * 4);
        }
    };

    auto comp = [&](int buf) {
        const float* swp = sm + buf * BUF2;
        const float* sxp = swp + 4608;
        int il = ks & 1, tqb = (ks >> 1) * 4;
#pragma unroll 1
        for (int tq = 0; tq < 4; ++tq) {
            int pl = il * 8 + tqb + tq;
            const float* xpl = sxp + pl * PLN;
            const float* wpl = swp + pl * 9 * 32 + ocg * 4;
#pragma unroll
            for (int dh = 0; dh < 3; ++dh) {
                const float* xr = xpl + (hh + dh) * 20;
                unsigned long long xp[9];
#pragma unroll
                for (int e = 0; e < 9; ++e)
                    xp[e] = *(const unsigned long long*)(xr + 2 * e);
#pragma unroll
                for (int dw = 0; dw < 3; ++dw) {
                    ulonglong2 wv = *(const ulonglong2*)(wpl + (dh * 3 + dw) * 32);
#pragma unroll
                    for (int w = 0; w < 7; ++w) {
                        fma2(acc[w][0], wv.x, xp[dw + w]);
                        fma2(acc[w][1], wv.y, xp[dw + w]);
                    }
                }
            }
        }
    };

    stage(0, 0); cpcommit();
#pragma unroll 1
    for (int ch = 0; ch < NCH2; ++ch) {
        if (ch + 1 < NCH2) { stage(ch + 1, (ch + 1) & 1); cpcommit(); cpwait1(); }
        else cpwait0();
        __syncthreads();
        comp(ch & 1);
        __syncthreads();
    }

    float f[28];
#pragma unroll
    for (int w = 0; w < 7; ++w) {
        unpack2(acc[w][0], f[w * 4 + 0], f[w * 4 + 1]);
        unpack2(acc[w][1], f[w * 4 + 2], f[w * 4 + 3]);
    }

    if (ks > 0) {
        float* dst = &sm[((ks - 1) * 56 + hh * 8 + ocg) * 29];
#pragma unroll
        for (int j = 0; j < 28; ++j) dst[j] = f[j];
    }
    __syncthreads();
    if (ks == 0) {
        for (int s = 0; s < 3; ++s) {
            const float* src = &sm[(s * 56 + hh * 8 + ocg) * 29];
#pragma unroll
            for (int j = 0; j < 28; ++j) f[j] += src[j];
        }
        int ocb = octile * 32 + ocg * 4;
#pragma unroll
        for (int j = 0; j < 4; ++j)
#pragma unroll
            for (int w = 0; w < 7; ++w)
                g_p2[((size_t)(ts * 32 + b) * 512 + ocb + j) * 49 + hh * 7 + w] =
                    f[w * 4 + j];
    }
}

// ---------------------------------------------------------------------------
// Heads: reduce conv2 partials (+bias,relu), 1x1 convs, softmax, decode+clip.
// ---------------------------------------------------------------------------
__global__ __launch_bounds__(256) void heads_k(const float* __restrict__ cw,
                                               const float* __restrict__ cb,
                                               const float* __restrict__ bw,
                                               const float* __restrict__ bb,
                                               const float* __restrict__ b2,
                                               const float* __restrict__ info,
                                               float* __restrict__ out) {
    extern __shared__ float sm[];
    float* sf = sm;          // [512][49]
    float* ss = sm + 25088;  // [54][49]

    int b = blockIdx.x, tid = threadIdx.x;
    const float* p0 = g_p2 + (size_t)b * 512 * 49;
    const float* p1 = g_p2 + (size_t)(32 + b) * 512 * 49;
    for (int i = tid; i < 25088; i += 256)
        sf[i] = fmaxf(p0[i] + p1[i] + b2[i / 49], 0.f);
    __syncthreads();

    for (int idx = tid; idx < 54 * 49; idx += 256) {
        int o = idx / 49, p = idx - o * 49;
        const float* wr = (o < 18) ? &cw[o * 512] : &bw[(o - 18) * 512];
        float bia = (o < 18) ? cb[o] : bb[o - 18];
        float a = 0.f;
        for (int c = 0; c < 512; ++c) a += sf[c * 49 + p] * __ldg(&wr[c]);
        ss[idx] = a + bia;
    }
    __syncthreads();

    for (int idx = tid; idx < 441; idx += 256) {
        int a9 = idx / 49, p = idx - a9 * 49;
        float bg = ss[a9 * 49 + p], fg = ss[(9 + a9) * 49 + p];
        float m = fmaxf(bg, fg);
        float e0 = expf(bg - m), e1 = expf(fg - m);
        float s = e0 + e1;
        out[CLS_OFF + b * 882 + a9 * 49 + p] = e0 / s;
        out[CLS_OFF + b * 882 + (9 + a9) * 49 + p] = e1 / s;
        g_scr[b * 441 + p * 9 + a9] = e1 / s;
    }
    for (int idx = tid; idx < 36 * 49; idx += 256)
        out[BBOX_OFF + b * 1764 + idx] = ss[882 + idx];

    float imh = info[b * 3 + 0], imw = info[b * 3 + 1];
    for (int i = tid; i < 441; i += 256) {
        int k = i / 9, a = i - k * 9;
        int hp = k / 7, wp = k - hp * 7;
        float d0 = ss[(18 + a * 4 + 0) * 49 + k];
        float d1 = ss[(18 + a * 4 + 1) * 49 + k];
        float d2 = ss[(18 + a * 4 + 2) * 49 + k];
        float d3 = ss[(18 + a * 4 + 3) * 49 + k];
        float x1 = c_anch[a][0] + wp * 16.f, y1 = c_anch[a][1] + hp * 16.f;
        float x2 = c_anch[a][2] + wp * 16.f, y2 = c_anch[a][3] + hp * 16.f;
        float aw = x2 - x1 + 1.f, ah = y2 - y1 + 1.f;
        float cx = x1 + 0.5f * aw, cy = y1 + 0.5f * ah;
        float pcx = d0 * aw + cx, pcy = d1 * ah + cy;
        float pw = expf(d2) * aw, ph = expf(d3) * ah;
        float bx1 = fminf(fmaxf(pcx - 0.5f * pw, 0.f), imw - 1.f);
        float by1 = fminf(fmaxf(pcy - 0.5f * ph, 0.f), imh - 1.f);
        float bx2 = fminf(fmaxf(pcx + 0.5f * pw, 0.f), imw - 1.f);
        float by2 = fminf(fmaxf(pcy + 0.5f * ph, 0.f), imh - 1.f);
        float* pr = &g_prop[(b * 441 + i) * 4];
        pr[0] = bx1; pr[1] = by1; pr[2] = bx2; pr[3] = by2;
    }
}

// ---------------------------------------------------------------------------
// NMS: stable rank-sort (score desc, idx asc), greedy, compact.
// ---------------------------------------------------------------------------
__global__ __launch_bounds__(448) void nms_k(float* __restrict__ out) {
    __shared__ float ux1[441], uy1[441], ux2[441], uy2[441], usc[441];
    __shared__ float sx1[441], sy1[441], sx2[441], sy2[441], sar[441];
    __shared__ int keep[441];

    int b = blockIdx.x, tid = threadIdx.x;
    for (int i = tid; i < 441; i += 448) {
        const float* pr = &g_prop[(b * 441 + i) * 4];
        ux1[i] = pr[0]; uy1[i] = pr[1]; ux2[i] = pr[2]; uy2[i] = pr[3];
        usc[i] = g_scr[b * 441 + i];
        keep[i] = 1;
    }
    __syncthreads();

    for (int i = tid; i < 441; i += 448) {
        float si = usc[i];
        int r = 0;
        for (int j = 0; j < 441; ++j) {
            float sj = usc[j];
            r += (sj > si) || (sj == si && j < i);
        }
        sx1[r] = ux1[i]; sy1[r] = uy1[i]; sx2[r] = ux2[i]; sy2[r] = uy2[i];
        sar[r] = (ux2[i] - ux1[i] + 1.f) * (uy2[i] - uy1[i] + 1.f);
    }

    for (int i = 0; i < 440; ++i) {
        __syncthreads();
        if (keep[i]) {
            float xi1 = sx1[i], yi1 = sy1[i], xi2 = sx2[i], yi2 = sy2[i], ai = sar[i];
            for (int j = i + 1 + tid; j < 441; j += 448) {
                if (!keep[j]) continue;
                float xx1 = fmaxf(xi1, sx1[j]);
                float yy1 = fmaxf(yi1, sy1[j]);
                float xx2 = fminf(xi2, sx2[j]);
                float yy2 = fminf(yi2, sy2[j]);
                float iw = fmaxf(xx2 - xx1 + 1.f, 0.f);
                float ih = fmaxf(yy2 - yy1 + 1.f, 0.f);
                float inter = iw * ih;
                float iou = inter / (ai + sar[j] - inter);
                if (iou > 0.7f) keep[j] = 0;
            }
        }
    }
    __syncthreads();

    for (int r = tid; r < 300; r += 448) {
        float* o = &out[ROIS_OFF + (b * 300 + r) * 5];
        o[0] = (float)b; o[1] = 0.f; o[2] = 0.f; o[3] = 0.f; o[4] = 0.f;
    }
    __syncthreads();
    for (int i = tid; i < 441; i += 448) {
        if (keep[i]) {
            int pos = 0;
            for (int j = 0; j < i; ++j) pos += keep[j];
            if (pos < 300) {
                float* o = &out[ROIS_OFF + (b * 300 + pos) * 5];
                o[1] = sx1[i]; o[2] = sy1[i]; o[3] = sx2[i]; o[4] = sy2[i];
            }
        }
    }
}

// ---------------------------------------------------------------------------
// Launch
// ---------------------------------------------------------------------------
extern "C" void kernel_launch(void* const* d_in, const int* in_sizes, int n_in,
                              void* d_out, int out_size) {
    const float* base = (const float*)d_in[0];
    const float* info = (const float*)d_in[1];
    const float* w1   = (const float*)d_in[4];
    const float* b1   = (const float*)d_in[5];
    const float* w2   = (const float*)d_in[6];
    const float* b2   = (const float*)d_in[7];
    const float* cw   = (const float*)d_in[8];
    const float* cb   = (const float*)d_in[9];
    const float* bw   = (const float*)d_in[10];
    const float* bb   = (const float*)d_in[11];
    float* out = (float*)d_out;

    cudaFuncSetAttribute(conv1_k, cudaFuncAttributeMaxDynamicSharedMemorySize, 2 * BUF1 * 4);
    cudaFuncSetAttribute(conv2_k, cudaFuncAttributeMaxDynamicSharedMemorySize, 2 * BUF2 * 4);
    cudaFuncSetAttribute(heads_k, cudaFuncAttributeMaxDynamicSharedMemorySize, 110936);

    float *pw1t = nullptr, *pw2t = nullptr;
    cudaGetSymbolAddress((void**)&pw1t, g_w1t);
    cudaGetSymbolAddress((void**)&pw2t, g_w2t);

    dim3 tb(32, 8);
    tr_k<<<dim3(K1_ / 32, 16), tb>>>(w1, pw1t, K1_);
    tr_k<<<dim3(K2_ / 32, 16), tb>>>(w2, pw2t, K2_);
    pad_in_k<<<221184, 256>>>(base);
    zero_xpad_k<<<49152, 256>>>();
    conv1_k<<<dim3(16, 512), 224, 2 * BUF1 * 4>>>(b1);
    conv2_k<<<dim3(16, 32, 2), 224, 2 * BUF2 * 4>>>();
    heads_k<<<32, 256, 110936>>>(cw, cb, bw, bb, b2, info, out);
    nms_k<<<32, 448>>>(out);
}

// round 5
// speedup vs baseline: 1.0268x; 1.0008x over previous
#include <cuda_runtime.h>
#include <cstdint>
#include <cstddef>

// ---------------------------------------------------------------------------
// Problem dims
// ---------------------------------------------------------------------------
#define B_  32
#define C_  512
#define T_  16
#define NA_ 441
#define K1_ 13824            // 512*27
#define K2_ 73728            // 512*16*9

// output layout: rois [32,300,5] | cls_prob [32,18,7,7] | bbox_pred [32,36,7,7]
#define ROIS_OFF 0
#define CLS_OFF  48000
#define BBOX_OFF 76224

// padded/duplicated plane: 9 rows x 10 cols (col9=0), each value duplicated
// -> 9*20 = 180 floats, padded to 192 (16B multiple). Pair (x,x) via LDS.64.
#define PLN 192

// conv1 tiling
#define BUF1 5760            // floats per buffer: 108*32 weights + 4*3*192 x
#define NCH1 128
// conv2 tiling
#define BUF2 7680            // floats per buffer: 144*32 weights + 2*8*192 x
#define NCH2 256

// ---------------------------------------------------------------------------
// Scratch (static device globals; no allocation)
// ---------------------------------------------------------------------------
__device__ float g_w1t[(size_t)K1_ * C_];                  // [k][oc]
__device__ float g_w2t[(size_t)K2_ * C_];                  // [k][oc]
__device__ float g_bfpad[(size_t)B_ * C_ * 18 * PLN];      // padded+dup input (t in [-1,16])
__device__ float g_xpad [(size_t)B_ * C_ * 16 * PLN];      // padded+dup conv1 output
__device__ float g_p2   [(size_t)2 * B_ * C_ * 49];        // conv2 t-split partials
__device__ float g_prop[B_ * NA_ * 4];
__device__ float g_scr [B_ * NA_];

__constant__ float c_anch[9][4] = {
    {-38.f,  -16.f,  53.f,  31.f},
    {-84.f,  -40.f,  99.f,  55.f},
    {-176.f, -88.f,  191.f, 103.f},
    {-24.f,  -24.f,  39.f,  39.f},
    {-56.f,  -56.f,  71.f,  71.f},
    {-120.f, -120.f, 135.f, 135.f},
    {-14.f,  -36.f,  29.f,  51.f},
    {-36.f,  -80.f,  51.f,  95.f},
    {-80.f,  -168.f, 95.f,  183.f}};

// ---------------------------------------------------------------------------
// PTX helpers
// ---------------------------------------------------------------------------
__device__ __forceinline__ void fma2(unsigned long long& d,
                                     unsigned long long a,
                                     unsigned long long b) {
    asm("fma.rn.f32x2 %0,%1,%2,%0;" : "+l"(d) : "l"(a), "l"(b));
}
__device__ __forceinline__ void unpack2(unsigned long long v, float& lo, float& hi) {
    asm("mov.b64 {%0,%1},%2;" : "=f"(lo), "=f"(hi) : "l"(v));
}
__device__ __forceinline__ void cpa16(unsigned dst, const void* src) {
    asm volatile("cp.async.cg.shared.global [%0],[%1],16;" :: "r"(dst), "l"(src));
}
__device__ __forceinline__ void cpcommit() { asm volatile("cp.async.commit_group;"); }
__device__ __forceinline__ void cpwait1()  { asm volatile("cp.async.wait_group 1;"); }
__device__ __forceinline__ void cpwait0()  { asm volatile("cp.async.wait_group 0;"); }

// ---------------------------------------------------------------------------
// Weight transpose: in [512][K] -> out [K][512]
// ---------------------------------------------------------------------------
__global__ void tr_k(const float* __restrict__ in, float* __restrict__ out, int K) {
    __shared__ float t[32][33];
    int kb = blockIdx.x << 5, ob = blockIdx.y << 5;
    int tx = threadIdx.x, ty = threadIdx.y;
#pragma unroll
    for (int j = 0; j < 32; j += 8)
        t[ty + j][tx] = in[(size_t)(ob + ty + j) * K + kb + tx];
    __syncthreads();
#pragma unroll
    for (int j = 0; j < 32; j += 8)
        out[(size_t)(kb + ty + j) * 512 + ob + tx] = t[tx][ty + j];
}

// ---------------------------------------------------------------------------
// Build padded+duplicated input planes. 1 float per thread.
// plane layout: row r (0..8) x col (0..9, col9=0), duplicated -> j = r*20 + 2*col{+1}
// ---------------------------------------------------------------------------
__global__ void pad_in_k(const float* __restrict__ bf) {
    size_t i = (size_t)blockIdx.x * 256 + threadIdx.x;   // total = 32*512*18*192
    int j = (int)(i % PLN);
    size_t r1 = i / PLN;
    int tp = (int)(r1 % 18);
    size_t bc = r1 / 18;
    float v = 0.f;
    if (j < 180 && tp >= 1 && tp <= 16) {
        int row = j / 20, col = (j % 20) >> 1;
        if (row >= 1 && row <= 7 && col >= 1 && col <= 7)
            v = bf[bc * 784 + (size_t)(tp - 1) * 49 + (row - 1) * 7 + (col - 1)];
    }
    g_bfpad[i] = v;
}

// zero g_xpad (borders must be zero; interior rewritten by conv1)
__global__ void zero_xpad_k() {
    size_t i = (size_t)blockIdx.x * 256 + threadIdx.x;
    ((float4*)g_xpad)[i] = make_float4(0.f, 0.f, 0.f, 0.f);
}

// ---------------------------------------------------------------------------
// Conv1: 3x3x3 pad(1,1,1) relu. grid=(16 oc-tiles, 512 (b,t)), block=224
// 8 ocg x 7 h x 4 ks; thread: 4 oc x 7 w. cp.async double buffered.
// ---------------------------------------------------------------------------
__global__ __launch_bounds__(224, 3) void conv1_k(const float* __restrict__ bias) {
    extern __shared__ float sm[];
    const int tid = threadIdx.x, ocg = tid & 7, hh = (tid >> 3) % 7, ks = tid / 56;
    const int octile = blockIdx.x, b = blockIdx.y >> 4, t = blockIdx.y & 15;
    const unsigned smb = (unsigned)__cvta_generic_to_shared(sm);

    unsigned long long acc[7][2];
#pragma unroll
    for (int w = 0; w < 7; ++w) { acc[w][0] = 0ull; acc[w][1] = 0ull; }

    auto stage = [&](int ch, int buf) {
        unsigned swd = smb + (unsigned)buf * (BUF1 * 4);
        unsigned sxd = swd + 3456 * 4;
        const float* wsrc = g_w1t + (size_t)(ch * 108) * 512 + octile * 32;
        for (int i = tid; i < 864; i += 224) {       // 108 rows x 32 fl (8x16B)
            int r = i >> 3, c = i & 7;
            cpa16(swd + (unsigned)(r * 128 + c * 16), wsrc + (size_t)r * 512 + c * 4);
        }
        const float* xsrc = g_bfpad + ((size_t)(b * 512 + ch * 4) * 18 + t) * PLN;
        for (int i = tid; i < 576; i += 224) {       // 12 planes x 48 chunks of 16B
            int p = i / 48, q = i - p * 48;
            int il = p / 3, dt = p - il * 3;
            cpa16(sxd + (unsigned)(p * 768 + q * 16),
                  xsrc + ((size_t)il * 18 + dt) * PLN + q * 4);
        }
    };

    auto comp = [&](int buf) {
        const float* swp = sm + buf * BUF1;
        const float* sxp = swp + 3456;
        const float* xic = sxp + ks * (3 * PLN);
        const float* wic = swp + ks * 27 * 32 + ocg * 4;
#pragma unroll 1
        for (int dt = 0; dt < 3; ++dt) {
#pragma unroll
            for (int dh = 0; dh < 3; ++dh) {
                const float* xr = xic + dt * PLN + (hh + dh) * 20;
                unsigned long long xp[9];
#pragma unroll
                for (int e = 0; e < 9; ++e)
                    xp[e] = *(const unsigned long long*)(xr + 2 * e);
#pragma unroll
                for (int dw = 0; dw < 3; ++dw) {
                    ulonglong2 wv =
                        *(const ulonglong2*)(wic + (dt * 9 + dh * 3 + dw) * 32);
#pragma unroll
                    for (int w = 0; w < 7; ++w) {
                        fma2(acc[w][0], wv.x, xp[dw + w]);
                        fma2(acc[w][1], wv.y, xp[dw + w]);
                    }
                }
            }
        }
    };

    stage(0, 0); cpcommit();
#pragma unroll 1
    for (int ch = 0; ch < NCH1; ++ch) {
        if (ch + 1 < NCH1) { stage(ch + 1, (ch + 1) & 1); cpcommit(); cpwait1(); }
        else cpwait0();
        __syncthreads();
        comp(ch & 1);
        __syncthreads();
    }

    float f[28];
#pragma unroll
    for (int w = 0; w < 7; ++w) {
        unpack2(acc[w][0], f[w * 4 + 0], f[w * 4 + 1]);
        unpack2(acc[w][1], f[w * 4 + 2], f[w * 4 + 3]);
    }

    if (ks > 0) {
        float* dst = &sm[((ks - 1) * 56 + hh * 8 + ocg) * 29];
#pragma unroll
        for (int j = 0; j < 28; ++j) dst[j] = f[j];
    }
    __syncthreads();
    if (ks == 0) {
        for (int s = 0; s < 3; ++s) {
            const float* src = &sm[(s * 56 + hh * 8 + ocg) * 29];
#pragma unroll
            for (int j = 0; j < 28; ++j) f[j] += src[j];
        }
        int ocb = octile * 32 + ocg * 4;
#pragma unroll
        for (int j = 0; j < 4; ++j) {
            float bv = bias[ocb + j];
#pragma unroll
            for (int w = 0; w < 7; ++w) {
                float v = fmaxf(f[w * 4 + j] + bv, 0.f);
                size_t o = ((size_t)(b * 512 + ocb + j) * 16 + t) * PLN
                           + (hh + 1) * 20 + 2 * (w + 1);
                g_xpad[o] = v; g_xpad[o + 1] = v;
            }
        }
    }
}

// ---------------------------------------------------------------------------
// Conv2: 16x3x3 pad(0,1,1). grid=(16 oc-tiles, 32 b, 2 t-split), block=224
// Each CTA: 8 t-planes. Partial sums (no bias/relu) -> g_p2.
// ---------------------------------------------------------------------------
__global__ __launch_bounds__(224, 3) void conv2_k() {
    extern __shared__ float sm[];
    const int tid = threadIdx.x, ocg = tid & 7, hh = (tid >> 3) % 7, ks = tid / 56;
    const int octile = blockIdx.x, b = blockIdx.y, ts = blockIdx.z, toff = ts * 8;
    const unsigned smb = (unsigned)__cvta_generic_to_shared(sm);

    unsigned long long acc[7][2];
#pragma unroll
    for (int w = 0; w < 7; ++w) { acc[w][0] = 0ull; acc[w][1] = 0ull; }

    auto stage = [&](int ch, int buf) {
        unsigned swd = smb + (unsigned)buf * (BUF2 * 4);
        unsigned sxd = swd + 4608 * 4;
        int icb = ch * 2;
        for (int i = tid; i < 1152; i += 224) {      // 144 rows x 32 fl
            int r = i >> 3, c = i & 7;
            int il = (r >= 72), rr = r - il * 72;
            size_t gk = ((size_t)(icb + il) * 16 + toff) * 9 + rr;
            cpa16(swd + (unsigned)(r * 128 + c * 16),
                  g_w2t + gk * 512 + octile * 32 + c * 4);
        }
        for (int i = tid; i < 768; i += 224) {       // 16 planes x 48 chunks of 16B
            int p = i / 48, q = i - p * 48;
            int il = p >> 3, tl = p & 7;
            cpa16(sxd + (unsigned)(p * 768 + q * 16),
                  g_xpad + ((size_t)(b * 512 + icb + il) * 16 + toff + tl) * PLN + q * 4);
        }
    };

    auto comp = [&](int buf) {
        const float* swp = sm + buf * BUF2;
        const float* sxp = swp + 4608;
        int il = ks & 1, tqb = (ks >> 1) * 4;
#pragma unroll 1
        for (int tq = 0; tq < 4; ++tq) {
            int pl = il * 8 + tqb + tq;
            const float* xpl = sxp + pl * PLN;
            const float* wpl = swp + pl * 9 * 32 + ocg * 4;
#pragma unroll
            for (int dh = 0; dh < 3; ++dh) {
                const float* xr = xpl + (hh + dh) * 20;
                unsigned long long xp[9];
#pragma unroll
                for (int e = 0; e < 9; ++e)
                    xp[e] = *(const unsigned long long*)(xr + 2 * e);
#pragma unroll
                for (int dw = 0; dw < 3; ++dw) {
                    ulonglong2 wv = *(const ulonglong2*)(wpl + (dh * 3 + dw) * 32);
#pragma unroll
                    for (int w = 0; w < 7; ++w) {
                        fma2(acc[w][0], wv.x, xp[dw + w]);
                        fma2(acc[w][1], wv.y, xp[dw + w]);
                    }
                }
            }
        }
    };

    stage(0, 0); cpcommit();
#pragma unroll 1
    for (int ch = 0; ch < NCH2; ++ch) {
        if (ch + 1 < NCH2) { stage(ch + 1, (ch + 1) & 1); cpcommit(); cpwait1(); }
        else cpwait0();
        __syncthreads();
        comp(ch & 1);
        __syncthreads();
    }

    float f[28];
#pragma unroll
    for (int w = 0; w < 7; ++w) {
        unpack2(acc[w][0], f[w * 4 + 0], f[w * 4 + 1]);
        unpack2(acc[w][1], f[w * 4 + 2], f[w * 4 + 3]);
    }

    if (ks > 0) {
        float* dst = &sm[((ks - 1) * 56 + hh * 8 + ocg) * 29];
#pragma unroll
        for (int j = 0; j < 28; ++j) dst[j] = f[j];
    }
    __syncthreads();
    if (ks == 0) {
        for (int s = 0; s < 3; ++s) {
            const float* src = &sm[(s * 56 + hh * 8 + ocg) * 29];
#pragma unroll
            for (int j = 0; j < 28; ++j) f[j] += src[j];
        }
        int ocb = octile * 32 + ocg * 4;
#pragma unroll
        for (int j = 0; j < 4; ++j)
#pragma unroll
            for (int w = 0; w < 7; ++w)
                g_p2[((size_t)(ts * 32 + b) * 512 + ocb + j) * 49 + hh * 7 + w] =
                    f[w * 4 + j];
    }
}

// ---------------------------------------------------------------------------
// Heads: reduce conv2 partials (+bias,relu), 1x1 convs, softmax, decode+clip.
// ---------------------------------------------------------------------------
__global__ __launch_bounds__(256) void heads_k(const float* __restrict__ cw,
                                               const float* __restrict__ cb,
                                               const float* __restrict__ bw,
                                               const float* __restrict__ bb,
                                               const float* __restrict__ b2,
                                               const float* __restrict__ info,
                                               float* __restrict__ out) {
    extern __shared__ float sm[];
    float* sf = sm;          // [512][49]
    float* ss = sm + 25088;  // [54][49]

    int b = blockIdx.x, tid = threadIdx.x;
    const float* p0 = g_p2 + (size_t)b * 512 * 49;
    const float* p1 = g_p2 + (size_t)(32 + b) * 512 * 49;
    for (int i = tid; i < 25088; i += 256)
        sf[i] = fmaxf(p0[i] + p1[i] + b2[i / 49], 0.f);
    __syncthreads();

    for (int idx = tid; idx < 54 * 49; idx += 256) {
        int o = idx / 49, p = idx - o * 49;
        const float* wr = (o < 18) ? &cw[o * 512] : &bw[(o - 18) * 512];
        float bia = (o < 18) ? cb[o] : bb[o - 18];
        float a = 0.f;
        for (int c = 0; c < 512; ++c) a += sf[c * 49 + p] * __ldg(&wr[c]);
        ss[idx] = a + bia;
    }
    __syncthreads();

    for (int idx = tid; idx < 441; idx += 256) {
        int a9 = idx / 49, p = idx - a9 * 49;
        float bg = ss[a9 * 49 + p], fg = ss[(9 + a9) * 49 + p];
        float m = fmaxf(bg, fg);
        float e0 = expf(bg - m), e1 = expf(fg - m);
        float s = e0 + e1;
        out[CLS_OFF + b * 882 + a9 * 49 + p] = e0 / s;
        out[CLS_OFF + b * 882 + (9 + a9) * 49 + p] = e1 / s;
        g_scr[b * 441 + p * 9 + a9] = e1 / s;
    }
    for (int idx = tid; idx < 36 * 49; idx += 256)
        out[BBOX_OFF + b * 1764 + idx] = ss[882 + idx];

    float imh = info[b * 3 + 0], imw = info[b * 3 + 1];
    for (int i = tid; i < 441; i += 256) {
        int k = i / 9, a = i - k * 9;
        int hp = k / 7, wp = k - hp * 7;
        float d0 = ss[(18 + a * 4 + 0) * 49 + k];
        float d1 = ss[(18 + a * 4 + 1) * 49 + k];
        float d2 = ss[(18 + a * 4 + 2) * 49 + k];
        float d3 = ss[(18 + a * 4 + 3) * 49 + k];
        float x1 = c_anch[a][0] + wp * 16.f, y1 = c_anch[a][1] + hp * 16.f;
        float x2 = c_anch[a][2] + wp * 16.f, y2 = c_anch[a][3] + hp * 16.f;
        float aw = x2 - x1 + 1.f, ah = y2 - y1 + 1.f;
        float cx = x1 + 0.5f * aw, cy = y1 + 0.5f * ah;
        float pcx = d0 * aw + cx, pcy = d1 * ah + cy;
        float pw = expf(d2) * aw, ph = expf(d3) * ah;
        float bx1 = fminf(fmaxf(pcx - 0.5f * pw, 0.f), imw - 1.f);
        float by1 = fminf(fmaxf(pcy - 0.5f * ph, 0.f), imh - 1.f);
        float bx2 = fminf(fmaxf(pcx + 0.5f * pw, 0.f), imw - 1.f);
        float by2 = fminf(fmaxf(pcy + 0.5f * ph, 0.f), imh - 1.f);
        float* pr = &g_prop[(b * 441 + i) * 4];
        pr[0] = bx1; pr[1] = by1; pr[2] = bx2; pr[3] = by2;
    }
}

// ---------------------------------------------------------------------------
// NMS: stable rank-sort (score desc, idx asc), greedy, compact.
// ---------------------------------------------------------------------------
__global__ __launch_bounds__(448) void nms_k(float* __restrict__ out) {
    __shared__ float ux1[441], uy1[441], ux2[441], uy2[441], usc[441];
    __shared__ float sx1[441], sy1[441], sx2[441], sy2[441], sar[441];
    __shared__ int keep[441];

    int b = blockIdx.x, tid = threadIdx.x;
    for (int i = tid; i < 441; i += 448) {
        const float* pr = &g_prop[(b * 441 + i) * 4];
        ux1[i] = pr[0]; uy1[i] = pr[1]; ux2[i] = pr[2]; uy2[i] = pr[3];
        usc[i] = g_scr[b * 441 + i];
        keep[i] = 1;
    }
    __syncthreads();

    for (int i = tid; i < 441; i += 448) {
        float si = usc[i];
        int r = 0;
        for (int j = 0; j < 441; ++j) {
            float sj = usc[j];
            r += (sj > si) || (sj == si && j < i);
        }
        sx1[r] = ux1[i]; sy1[r] = uy1[i]; sx2[r] = ux2[i]; sy2[r] = uy2[i];
        sar[r] = (ux2[i] - ux1[i] + 1.f) * (uy2[i] - uy1[i] + 1.f);
    }

    for (int i = 0; i < 440; ++i) {
        __syncthreads();
        if (keep[i]) {
            float xi1 = sx1[i], yi1 = sy1[i], xi2 = sx2[i], yi2 = sy2[i], ai = sar[i];
            for (int j = i + 1 + tid; j < 441; j += 448) {
                if (!keep[j]) continue;
                float xx1 = fmaxf(xi1, sx1[j]);
                float yy1 = fmaxf(yi1, sy1[j]);
                float xx2 = fminf(xi2, sx2[j]);
                float yy2 = fminf(yi2, sy2[j]);
                float iw = fmaxf(xx2 - xx1 + 1.f, 0.f);
                float ih = fmaxf(yy2 - yy1 + 1.f, 0.f);
                float inter = iw * ih;
                float iou = inter / (ai + sar[j] - inter);
                if (iou > 0.7f) keep[j] = 0;
            }
        }
    }
    __syncthreads();

    for (int r = tid; r < 300; r += 448) {
        float* o = &out[ROIS_OFF + (b * 300 + r) * 5];
        o[0] = (float)b; o[1] = 0.f; o[2] = 0.f; o[3] = 0.f; o[4] = 0.f;
    }
    __syncthreads();
    for (int i = tid; i < 441; i += 448) {
        if (keep[i]) {
            int pos = 0;
            for (int j = 0; j < i; ++j) pos += keep[j];
            if (pos < 300) {
                float* o = &out[ROIS_OFF + (b * 300 + pos) * 5];
                o[1] = sx1[i]; o[2] = sy1[i]; o[3] = sx2[i]; o[4] = sy2[i];
            }
        }
    }
}

// ---------------------------------------------------------------------------
// Launch
// ---------------------------------------------------------------------------
extern "C" void kernel_launch(void* const* d_in, const int* in_sizes, int n_in,
                              void* d_out, int out_size) {
    const float* base = (const float*)d_in[0];
    const float* info = (const float*)d_in[1];
    const float* w1   = (const float*)d_in[4];
    const float* b1   = (const float*)d_in[5];
    const float* w2   = (const float*)d_in[6];
    const float* b2   = (const float*)d_in[7];
    const float* cw   = (const float*)d_in[8];
    const float* cb   = (const float*)d_in[9];
    const float* bw   = (const float*)d_in[10];
    const float* bb   = (const float*)d_in[11];
    float* out = (float*)d_out;

    cudaFuncSetAttribute(conv1_k, cudaFuncAttributeMaxDynamicSharedMemorySize, 2 * BUF1 * 4);
    cudaFuncSetAttribute(conv2_k, cudaFuncAttributeMaxDynamicSharedMemorySize, 2 * BUF2 * 4);
    cudaFuncSetAttribute(heads_k, cudaFuncAttributeMaxDynamicSharedMemorySize, 110936);

    float *pw1t = nullptr, *pw2t = nullptr;
    cudaGetSymbolAddress((void**)&pw1t, g_w1t);
    cudaGetSymbolAddress((void**)&pw2t, g_w2t);

    dim3 tb(32, 8);
    tr_k<<<dim3(K1_ / 32, 16), tb>>>(w1, pw1t, K1_);
    tr_k<<<dim3(K2_ / 32, 16), tb>>>(w2, pw2t, K2_);
    pad_in_k<<<221184, 256>>>(base);
    zero_xpad_k<<<49152, 256>>>();
    conv1_k<<<dim3(16, 512), 224, 2 * BUF1 * 4>>>(b1);
    conv2_k<<<dim3(16, 32, 2), 224, 2 * BUF2 * 4>>>();
    heads_k<<<32, 256, 110936>>>(cw, cb, bw, bb, b2, info, out);
    nms_k<<<32, 448>>>(out);
}

// round 6
// speedup vs baseline: 1.0836x; 1.0553x over previous
#include <cuda_runtime.h>
#include <cstdint>
#include <cstddef>

// ---------------------------------------------------------------------------
// Problem dims
// ---------------------------------------------------------------------------
#define B_  32
#define C_  512
#define T_  16
#define NA_ 441
#define K1_ 13824            // 512*27
#define K2_ 73728            // 512*16*9

// output layout: rois [32,300,5] | cls_prob [32,18,7,7] | bbox_pred [32,36,7,7]
#define ROIS_OFF 0
#define CLS_OFF  48000
#define BBOX_OFF 76224

// padded/duplicated plane: 9 rows x 10 cols (col9=0), each value duplicated
// -> 9*20 = 180 floats, padded to 192 (16B multiple). Pair (x,x) via LDS.64.
#define PLN 192

// conv1 tiling: chunk = 4 ic; weights 108 rows x 64 oc + x 12 planes
#define BUF1 9216            // floats per buffer: 6912 w + 2304 x
#define NCH1 128
// conv2 tiling: chunk = 2 ic x 4 t; weights 72 rows x 64 oc + x 8 planes
#define BUF2 6144            // floats per buffer: 4608 w + 1536 x
#define NCH2 256

// ---------------------------------------------------------------------------
// Scratch (static device globals; no allocation)
// ---------------------------------------------------------------------------
__device__ float g_w1t[(size_t)K1_ * C_];                  // [k][oc]
__device__ float g_w2t[(size_t)K2_ * C_];                  // [k][oc]
__device__ float g_bfpad[(size_t)B_ * C_ * 18 * PLN];      // padded+dup input (t in [-1,16])
__device__ float g_xpad [(size_t)B_ * C_ * 16 * PLN];      // padded+dup conv1 output
__device__ float g_p2   [(size_t)4 * B_ * C_ * 49];        // conv2 t-split partials
__device__ float g_prop[B_ * NA_ * 4];
__device__ float g_scr [B_ * NA_];

__constant__ float c_anch[9][4] = {
    {-38.f,  -16.f,  53.f,  31.f},
    {-84.f,  -40.f,  99.f,  55.f},
    {-176.f, -88.f,  191.f, 103.f},
    {-24.f,  -24.f,  39.f,  39.f},
    {-56.f,  -56.f,  71.f,  71.f},
    {-120.f, -120.f, 135.f, 135.f},
    {-14.f,  -36.f,  29.f,  51.f},
    {-36.f,  -80.f,  51.f,  95.f},
    {-80.f,  -168.f, 95.f,  183.f}};

// ---------------------------------------------------------------------------
// PTX helpers
// ---------------------------------------------------------------------------
__device__ __forceinline__ void fma2(unsigned long long& d,
                                     unsigned long long a,
                                     unsigned long long b) {
    asm("fma.rn.f32x2 %0,%1,%2,%0;" : "+l"(d) : "l"(a), "l"(b));
}
__device__ __forceinline__ void unpack2(unsigned long long v, float& lo, float& hi) {
    asm("mov.b64 {%0,%1},%2;" : "=f"(lo), "=f"(hi) : "l"(v));
}
__device__ __forceinline__ void cpa16(unsigned dst, const void* src) {
    asm volatile("cp.async.cg.shared.global [%0],[%1],16;" :: "r"(dst), "l"(src));
}
__device__ __forceinline__ void cpcommit() { asm volatile("cp.async.commit_group;"); }
__device__ __forceinline__ void cpwait1()  { asm volatile("cp.async.wait_group 1;"); }
__device__ __forceinline__ void cpwait0()  { asm volatile("cp.async.wait_group 0;"); }

// ---------------------------------------------------------------------------
// Weight transpose: in [512][K] -> out [K][512]
// ---------------------------------------------------------------------------
__global__ void tr_k(const float* __restrict__ in, float* __restrict__ out, int K) {
    __shared__ float t[32][33];
    int kb = blockIdx.x << 5, ob = blockIdx.y << 5;
    int tx = threadIdx.x, ty = threadIdx.y;
#pragma unroll
    for (int j = 0; j < 32; j += 8)
        t[ty + j][tx] = in[(size_t)(ob + ty + j) * K + kb + tx];
    __syncthreads();
#pragma unroll
    for (int j = 0; j < 32; j += 8)
        out[(size_t)(kb + ty + j) * 512 + ob + tx] = t[tx][ty + j];
}

// ---------------------------------------------------------------------------
// Build padded+duplicated input planes. 1 float per thread.
// ---------------------------------------------------------------------------
__global__ void pad_in_k(const float* __restrict__ bf) {
    size_t i = (size_t)blockIdx.x * 256 + threadIdx.x;   // total = 32*512*18*192
    int j = (int)(i % PLN);
    size_t r1 = i / PLN;
    int tp = (int)(r1 % 18);
    size_t bc = r1 / 18;
    float v = 0.f;
    if (j < 180 && tp >= 1 && tp <= 16) {
        int row = j / 20, col = (j % 20) >> 1;
        if (row >= 1 && row <= 7 && col >= 1 && col <= 7)
            v = bf[bc * 784 + (size_t)(tp - 1) * 49 + (row - 1) * 7 + (col - 1)];
    }
    g_bfpad[i] = v;
}

// zero g_xpad (borders must be zero; interior rewritten by conv1)
__global__ void zero_xpad_k() {
    size_t i = (size_t)blockIdx.x * 256 + threadIdx.x;
    ((float4*)g_xpad)[i] = make_float4(0.f, 0.f, 0.f, 0.f);
}

// ---------------------------------------------------------------------------
// Conv1: 3x3x3 pad(1,1,1) relu. grid=(8 oc-tiles, 512 (b,t)), block=224
// 8 ocg x 7 h x 4 ks; thread: 8 oc x 7 w. cp.async double buffered.
// ---------------------------------------------------------------------------
__global__ __launch_bounds__(224, 2) void conv1_k(const float* __restrict__ bias) {
    extern __shared__ float sm[];
    const int tid = threadIdx.x, ocg = tid & 7, hh = (tid >> 3) % 7, ks = tid / 56;
    const int octile = blockIdx.x, b = blockIdx.y >> 4, t = blockIdx.y & 15;
    const unsigned smb = (unsigned)__cvta_generic_to_shared(sm);

    unsigned long long acc[7][4];
#pragma unroll
    for (int w = 0; w < 7; ++w)
#pragma unroll
        for (int q = 0; q < 4; ++q) acc[w][q] = 0ull;

    auto stage = [&](int ch, int buf) {
        unsigned swd = smb + (unsigned)buf * (BUF1 * 4);
        unsigned sxd = swd + 6912 * 4;
        const float* wsrc = g_w1t + (size_t)(ch * 108) * 512 + octile * 64;
        for (int i = tid; i < 1728; i += 224) {      // 108 rows x 64 fl (16x16B)
            int r = i >> 4, c = i & 15;
            cpa16(swd + (unsigned)(r * 256 + c * 16), wsrc + (size_t)r * 512 + c * 4);
        }
        const float* xsrc = g_bfpad + ((size_t)(b * 512 + ch * 4) * 18 + t) * PLN;
        for (int i = tid; i < 576; i += 224) {       // 12 planes x 48 chunks of 16B
            int p = i / 48, q = i - p * 48;
            int il = p / 3, dt = p - il * 3;
            cpa16(sxd + (unsigned)(p * 768 + q * 16),
                  xsrc + ((size_t)il * 18 + dt) * PLN + q * 4);
        }
    };

    auto comp = [&](int buf) {
        const float* swp = sm + buf * BUF1;
        const float* sxp = swp + 6912;
        const float* xic = sxp + ks * (3 * PLN);
        const float* wic = swp + ks * 27 * 64 + ocg * 8;
#pragma unroll 1
        for (int dt = 0; dt < 3; ++dt) {
#pragma unroll
            for (int dh = 0; dh < 3; ++dh) {
                const float* xr = xic + dt * PLN + (hh + dh) * 20;
                unsigned long long xp[9];
#pragma unroll
                for (int e = 0; e < 9; ++e)
                    xp[e] = *(const unsigned long long*)(xr + 2 * e);
#pragma unroll
                for (int dw = 0; dw < 3; ++dw) {
                    const ulonglong2* wp =
                        (const ulonglong2*)(wic + (dt * 9 + dh * 3 + dw) * 64);
                    ulonglong2 wa = wp[0], wb = wp[1];
#pragma unroll
                    for (int w = 0; w < 7; ++w) {
                        fma2(acc[w][0], wa.x, xp[dw + w]);
                        fma2(acc[w][1], wa.y, xp[dw + w]);
                        fma2(acc[w][2], wb.x, xp[dw + w]);
                        fma2(acc[w][3], wb.y, xp[dw + w]);
                    }
                }
            }
        }
    };

    stage(0, 0); cpcommit();
#pragma unroll 1
    for (int ch = 0; ch < NCH1; ++ch) {
        if (ch + 1 < NCH1) { stage(ch + 1, (ch + 1) & 1); cpcommit(); cpwait1(); }
        else cpwait0();
        __syncthreads();
        comp(ch & 1);
        __syncthreads();
    }

    float f[56];
#pragma unroll
    for (int w = 0; w < 7; ++w)
#pragma unroll
        for (int q = 0; q < 4; ++q)
            unpack2(acc[w][q], f[w * 8 + q * 2], f[w * 8 + q * 2 + 1]);

    if (ks > 0) {
        float* dst = &sm[((ks - 1) * 56 + hh * 8 + ocg) * 57];
#pragma unroll
        for (int j = 0; j < 56; ++j) dst[j] = f[j];
    }
    __syncthreads();
    if (ks == 0) {
        for (int s = 0; s < 3; ++s) {
            const float* src = &sm[(s * 56 + hh * 8 + ocg) * 57];
#pragma unroll
            for (int j = 0; j < 56; ++j) f[j] += src[j];
        }
        int ocb = octile * 64 + ocg * 8;
#pragma unroll
        for (int j = 0; j < 8; ++j) {
            float bv = bias[ocb + j];
#pragma unroll
            for (int w = 0; w < 7; ++w) {
                float v = fmaxf(f[w * 8 + j] + bv, 0.f);
                size_t o = ((size_t)(b * 512 + ocb + j) * 16 + t) * PLN
                           + (hh + 1) * 20 + 2 * (w + 1);
                *(float2*)&g_xpad[o] = make_float2(v, v);
            }
        }
    }
}

// ---------------------------------------------------------------------------
// Conv2: 16x3x3 pad(0,1,1). grid=(8 oc-tiles, 32 b, 4 t-split), block=224
// Each CTA: 4 t-planes. Partial sums (no bias/relu) -> g_p2.
// ---------------------------------------------------------------------------
__global__ __launch_bounds__(224, 2) void conv2_k() {
    extern __shared__ float sm[];
    const int tid = threadIdx.x, ocg = tid & 7, hh = (tid >> 3) % 7, ks = tid / 56;
    const int octile = blockIdx.x, b = blockIdx.y, ts = blockIdx.z, toff = ts * 4;
    const unsigned smb = (unsigned)__cvta_generic_to_shared(sm);

    unsigned long long acc[7][4];
#pragma unroll
    for (int w = 0; w < 7; ++w)
#pragma unroll
        for (int q = 0; q < 4; ++q) acc[w][q] = 0ull;

    auto stage = [&](int ch, int buf) {
        unsigned swd = smb + (unsigned)buf * (BUF2 * 4);
        unsigned sxd = swd + 4608 * 4;
        int icb = ch * 2;
        for (int i = tid; i < 1152; i += 224) {      // 72 rows x 64 fl (16x16B)
            int r = i >> 4, c = i & 15;
            int il = r / 36, rr = r - il * 36;
            size_t gk = (size_t)(icb + il) * 144 + toff * 9 + rr;
            cpa16(swd + (unsigned)(r * 256 + c * 16),
                  g_w2t + gk * 512 + octile * 64 + c * 4);
        }
        for (int i = tid; i < 384; i += 224) {       // 8 planes x 48 chunks of 16B
            int p = i / 48, q = i - p * 48;
            int il = p >> 2, tl = p & 3;
            cpa16(sxd + (unsigned)(p * 768 + q * 16),
                  g_xpad + ((size_t)(b * 512 + icb + il) * 16 + toff + tl) * PLN + q * 4);
        }
    };

    auto comp = [&](int buf) {
        const float* swp = sm + buf * BUF2;
        const float* sxp = swp + 4608;
#pragma unroll 1
        for (int i2 = 0; i2 < 2; ++i2) {
            int pl = ks * 2 + i2;
            int il = pl >> 2, tl = pl & 3;
            const float* xpl = sxp + pl * PLN;
            const float* wpl = swp + (il * 36 + tl * 9) * 64 + ocg * 8;
#pragma unroll
            for (int dh = 0; dh < 3; ++dh) {
                const float* xr = xpl + (hh + dh) * 20;
                unsigned long long xp[9];
#pragma unroll
                for (int e = 0; e < 9; ++e)
                    xp[e] = *(const unsigned long long*)(xr + 2 * e);
#pragma unroll
                for (int dw = 0; dw < 3; ++dw) {
                    const ulonglong2* wp =
                        (const ulonglong2*)(wpl + (dh * 3 + dw) * 64);
                    ulonglong2 wa = wp[0], wb = wp[1];
#pragma unroll
                    for (int w = 0; w < 7; ++w) {
                        fma2(acc[w][0], wa.x, xp[dw + w]);
                        fma2(acc[w][1], wa.y, xp[dw + w]);
                        fma2(acc[w][2], wb.x, xp[dw + w]);
                        fma2(acc[w][3], wb.y, xp[dw + w]);
                    }
                }
            }
        }
    };

    stage(0, 0); cpcommit();
#pragma unroll 1
    for (int ch = 0; ch < NCH2; ++ch) {
        if (ch + 1 < NCH2) { stage(ch + 1, (ch + 1) & 1); cpcommit(); cpwait1(); }
        else cpwait0();
        __syncthreads();
        comp(ch & 1);
        __syncthreads();
    }

    float f[56];
#pragma unroll
    for (int w = 0; w < 7; ++w)
#pragma unroll
        for (int q = 0; q < 4; ++q)
            unpack2(acc[w][q], f[w * 8 + q * 2], f[w * 8 + q * 2 + 1]);

    if (ks > 0) {
        float* dst = &sm[((ks - 1) * 56 + hh * 8 + ocg) * 57];
#pragma unroll
        for (int j = 0; j < 56; ++j) dst[j] = f[j];
    }
    __syncthreads();
    if (ks == 0) {
        for (int s = 0; s < 3; ++s) {
            const float* src = &sm[(s * 56 + hh * 8 + ocg) * 57];
#pragma unroll
            for (int j = 0; j < 56; ++j) f[j] += src[j];
        }
        int ocb = octile * 64 + ocg * 8;
#pragma unroll
        for (int j = 0; j < 8; ++j)
#pragma unroll
            for (int w = 0; w < 7; ++w)
                g_p2[((size_t)(ts * 32 + b) * 512 + ocb + j) * 49 + hh * 7 + w] =
                    f[w * 8 + j];
    }
}

// ---------------------------------------------------------------------------
// Heads: reduce conv2 partials (+bias,relu), 1x1 convs, softmax, decode+clip.
// ---------------------------------------------------------------------------
__global__ __launch_bounds__(256) void heads_k(const float* __restrict__ cw,
                                               const float* __restrict__ cb,
                                               const float* __restrict__ bw,
                                               const float* __restrict__ bb,
                                               const float* __restrict__ b2,
                                               const float* __restrict__ info,
                                               float* __restrict__ out) {
    extern __shared__ float sm[];
    float* sf = sm;          // [512][49]
    float* ss = sm + 25088;  // [54][49]

    int b = blockIdx.x, tid = threadIdx.x;
    const float* p0 = g_p2 + (size_t)b * 512 * 49;
    const float* p1 = g_p2 + (size_t)(32 + b) * 512 * 49;
    const float* p2 = g_p2 + (size_t)(64 + b) * 512 * 49;
    const float* p3 = g_p2 + (size_t)(96 + b) * 512 * 49;
    for (int i = tid; i < 25088; i += 256)
        sf[i] = fmaxf((p0[i] + p1[i]) + (p2[i] + p3[i]) + b2[i / 49], 0.f);
    __syncthreads();

    for (int idx = tid; idx < 54 * 49; idx += 256) {
        int o = idx / 49, p = idx - o * 49;
        const float* wr = (o < 18) ? &cw[o * 512] : &bw[(o - 18) * 512];
        float bia = (o < 18) ? cb[o] : bb[o - 18];
        float a = 0.f;
        for (int c = 0; c < 512; ++c) a += sf[c * 49 + p] * __ldg(&wr[c]);
        ss[idx] = a + bia;
    }
    __syncthreads();

    for (int idx = tid; idx < 441; idx += 256) {
        int a9 = idx / 49, p = idx - a9 * 49;
        float bg = ss[a9 * 49 + p], fg = ss[(9 + a9) * 49 + p];
        float m = fmaxf(bg, fg);
        float e0 = expf(bg - m), e1 = expf(fg - m);
        float s = e0 + e1;
        out[CLS_OFF + b * 882 + a9 * 49 + p] = e0 / s;
        out[CLS_OFF + b * 882 + (9 + a9) * 49 + p] = e1 / s;
        g_scr[b * 441 + p * 9 + a9] = e1 / s;
    }
    for (int idx = tid; idx < 36 * 49; idx += 256)
        out[BBOX_OFF + b * 1764 + idx] = ss[882 + idx];

    float imh = info[b * 3 + 0], imw = info[b * 3 + 1];
    for (int i = tid; i < 441; i += 256) {
        int k = i / 9, a = i - k * 9;
        int hp = k / 7, wp = k - hp * 7;
        float d0 = ss[(18 + a * 4 + 0) * 49 + k];
        float d1 = ss[(18 + a * 4 + 1) * 49 + k];
        float d2 = ss[(18 + a * 4 + 2) * 49 + k];
        float d3 = ss[(18 + a * 4 + 3) * 49 + k];
        float x1 = c_anch[a][0] + wp * 16.f, y1 = c_anch[a][1] + hp * 16.f;
        float x2 = c_anch[a][2] + wp * 16.f, y2 = c_anch[a][3] + hp * 16.f;
        float aw = x2 - x1 + 1.f, ah = y2 - y1 + 1.f;
        float cx = x1 + 0.5f * aw, cy = y1 + 0.5f * ah;
        float pcx = d0 * aw + cx, pcy = d1 * ah + cy;
        float pw = expf(d2) * aw, ph = expf(d3) * ah;
        float bx1 = fminf(fmaxf(pcx - 0.5f * pw, 0.f), imw - 1.f);
        float by1 = fminf(fmaxf(pcy - 0.5f * ph, 0.f), imh - 1.f);
        float bx2 = fminf(fmaxf(pcx + 0.5f * pw, 0.f), imw - 1.f);
        float by2 = fminf(fmaxf(pcy + 0.5f * ph, 0.f), imh - 1.f);
        float* pr = &g_prop[(b * 441 + i) * 4];
        pr[0] = bx1; pr[1] = by1; pr[2] = bx2; pr[3] = by2;
    }
}

// ---------------------------------------------------------------------------
// NMS: stable rank-sort (score desc, idx asc), greedy, compact.
// ---------------------------------------------------------------------------
__global__ __launch_bounds__(448) void nms_k(float* __restrict__ out) {
    __shared__ float ux1[441], uy1[441], ux2[441], uy2[441], usc[441];
    __shared__ float sx1[441], sy1[441], sx2[441], sy2[441], sar[441];
    __shared__ int keep[441];

    int b = blockIdx.x, tid = threadIdx.x;
    for (int i = tid; i < 441; i += 448) {
        const float* pr = &g_prop[(b * 441 + i) * 4];
        ux1[i] = pr[0]; uy1[i] = pr[1]; ux2[i] = pr[2]; uy2[i] = pr[3];
        usc[i] = g_scr[b * 441 + i];
        keep[i] = 1;
    }
    __syncthreads();

    for (int i = tid; i < 441; i += 448) {
        float si = usc[i];
        int r = 0;
        for (int j = 0; j < 441; ++j) {
            float sj = usc[j];
            r += (sj > si) || (sj == si && j < i);
        }
        sx1[r] = ux1[i]; sy1[r] = uy1[i]; sx2[r] = ux2[i]; sy2[r] = uy2[i];
        sar[r] = (ux2[i] - ux1[i] + 1.f) * (uy2[i] - uy1[i] + 1.f);
    }

    for (int i = 0; i < 440; ++i) {
        __syncthreads();
        if (keep[i]) {
            float xi1 = sx1[i], yi1 = sy1[i], xi2 = sx2[i], yi2 = sy2[i], ai = sar[i];
            for (int j = i + 1 + tid; j < 441; j += 448) {
                if (!keep[j]) continue;
                float xx1 = fmaxf(xi1, sx1[j]);
                float yy1 = fmaxf(yi1, sy1[j]);
                float xx2 = fminf(xi2, sx2[j]);
                float yy2 = fminf(yi2, sy2[j]);
                float iw = fmaxf(xx2 - xx1 + 1.f, 0.f);
                float ih = fmaxf(yy2 - yy1 + 1.f, 0.f);
                float inter = iw * ih;
                float iou = inter / (ai + sar[j] - inter);
                if (iou > 0.7f) keep[j] = 0;
            }
        }
    }
    __syncthreads();

    for (int r = tid; r < 300; r += 448) {
        float* o = &out[ROIS_OFF + (b * 300 + r) * 5];
        o[0] = (float)b; o[1] = 0.f; o[2] = 0.f; o[3] = 0.f; o[4] = 0.f;
    }
    __syncthreads();
    for (int i = tid; i < 441; i += 448) {
        if (keep[i]) {
            int pos = 0;
            for (int j = 0; j < i; ++j) pos += keep[j];
            if (pos < 300) {
                float* o = &out[ROIS_OFF + (b * 300 + pos) * 5];
                o[1] = sx1[i]; o[2] = sy1[i]; o[3] = sx2[i]; o[4] = sy2[i];
            }
        }
    }
}

// ---------------------------------------------------------------------------
// Launch
// ---------------------------------------------------------------------------
extern "C" void kernel_launch(void* const* d_in, const int* in_sizes, int n_in,
                              void* d_out, int out_size) {
    const float* base = (const float*)d_in[0];
    const float* info = (const float*)d_in[1];
    const float* w1   = (const float*)d_in[4];
    const float* b1   = (const float*)d_in[5];
    const float* w2   = (const float*)d_in[6];
    const float* b2   = (const float*)d_in[7];
    const float* cw   = (const float*)d_in[8];
    const float* cb   = (const float*)d_in[9];
    const float* bw   = (const float*)d_in[10];
    const float* bb   = (const float*)d_in[11];
    float* out = (float*)d_out;

    cudaFuncSetAttribute(conv1_k, cudaFuncAttributeMaxDynamicSharedMemorySize, 2 * BUF1 * 4);
    cudaFuncSetAttribute(conv2_k, cudaFuncAttributeMaxDynamicSharedMemorySize, 2 * BUF2 * 4);
    cudaFuncSetAttribute(heads_k, cudaFuncAttributeMaxDynamicSharedMemorySize, 110936);

    float *pw1t = nullptr, *pw2t = nullptr;
    cudaGetSymbolAddress((void**)&pw1t, g_w1t);
    cudaGetSymbolAddress((void**)&pw2t, g_w2t);

    dim3 tb(32, 8);
    tr_k<<<dim3(K1_ / 32, 16), tb>>>(w1, pw1t, K1_);
    tr_k<<<dim3(K2_ / 32, 16), tb>>>(w2, pw2t, K2_);
    pad_in_k<<<221184, 256>>>(base);
    zero_xpad_k<<<49152, 256>>>();
    conv1_k<<<dim3(8, 512), 224, 2 * BUF1 * 4>>>(b1);
    conv2_k<<<dim3(8, 32, 4), 224, 2 * BUF2 * 4>>>();
    heads_k<<<32, 256, 110936>>>(cw, cb, bw, bb, b2, info, out);
    nms_k<<<32, 448>>>(out);
}